// round 8
// baseline (speedup 1.0000x reference)
#include <cuda_runtime.h>
#include <cuda_bf16.h>

#define NN 16500
#define NE 100000
#define KT 3
#define GEN_EPS 1e-7f
#define BN_EPS 1e-5f

// ---------------- scratch ----------------
__device__ int   d_cnt[KT][NN];
__device__ int   d_off[KT][NN + 1];
__device__ int   d_cur[KT][NN];
__device__ int   d_eid[KT][NE];
__device__ float d_agg[KT][NN * 256];
__device__ float d_hh[KT][NN * 512];
__device__ float d_accb[NN * 256];
__device__ float d_xcur[NN * 256];
__device__ float d_cs[KT * 512], d_css[KT * 512];
__device__ float d_scale[KT * 512], d_shift[KT * 512];

// ---------------- CSR build ----------------
__global__ void k_zero_counts() {
    int i = blockIdx.x * blockDim.x + threadIdx.x;
    if (i < KT * NN) ((int*)d_cnt)[i] = 0;
}

__global__ void k_count(const int* __restrict__ ei) {
    int i = blockIdx.x * blockDim.x + threadIdx.x;
    if (i >= KT * NE) return;
    int k = i / NE, e = i % NE;
    atomicAdd(&d_cnt[k][ei[k * 2 * NE + NE + e]], 1);
}

__global__ void k_scan() {
    __shared__ int sh[1024];
    int k = blockIdx.x, tid = threadIdx.x;
    int carry = 0;
    if (tid == 0) d_off[k][0] = 0;
    for (int base = 0; base < NN; base += 1024) {
        int i = base + tid;
        int v = (i < NN) ? d_cnt[k][i] : 0;
        sh[tid] = v;
        __syncthreads();
        for (int o = 1; o < 1024; o <<= 1) {
            int t = (tid >= o) ? sh[tid - o] : 0;
            __syncthreads();
            sh[tid] += t;
            __syncthreads();
        }
        int inc = sh[tid];
        int tot = sh[1023];
        if (i < NN) {
            d_off[k][i + 1] = carry + inc;
            d_cur[k][i]     = carry + inc - v;
        }
        __syncthreads();
        carry += tot;
    }
}

__global__ void k_fill(const int* __restrict__ ei) {
    int i = blockIdx.x * blockDim.x + threadIdx.x;
    if (i >= KT * NE) return;
    int k = i / NE, e = i % NE;
    int pos = atomicAdd(&d_cur[k][ei[k * 2 * NE + NE + e]], 1);
    d_eid[k][pos] = e;
}

// ------------- batched GENConv aggregation (online segment softmax) ----------
__global__ void k_aggr(const float* __restrict__ xin,
                       const int* __restrict__ ei,
                       const float* __restrict__ ea,
                       const float* __restrict__ WeB,
                       const float* __restrict__ beB,
                       int ci) {
    int n = blockIdx.x;
    int k = blockIdx.y;
    int c = threadIdx.x;
    if (c >= ci) return;
    const int*   src = ei + k * 2 * NE;
    const float* eak = ea + k * NE;
    float we = WeB[k * ci + c], bec = beB[k * ci + c];
    float xn = xin[n * ci + c];
    float v = fmaxf(xn + we + bec, 0.f) + GEN_EPS;  // self loop (ea = 1)
    float m = v, den = 1.f, ws = v;
    int j0 = d_off[k][n], j1 = d_off[k][n + 1];
    for (int j = j0; j < j1; j++) {
        int e = d_eid[k][j];
        int s = src[e];
        float a = eak[e];
        float u = fmaxf(xin[s * ci + c] + a * we + bec, 0.f) + GEN_EPS;
        float nm = fmaxf(m, u);
        float sa = __expf(m - nm);
        float sb = __expf(u - nm);
        den = den * sa + sb;
        ws  = ws * sa + u * sb;
        m = nm;
    }
    d_agg[k][n * ci + c] = ws / den + xn;
}

// ---------------- tf32 3x-split tensor-core GEMM machinery ----------------
#define BM 128
#define BN 128
#define BK 16

__device__ __forceinline__ void split_tf32(float v, unsigned& hi, unsigned& lo) {
    asm("cvt.rna.tf32.f32 %0, %1;" : "=r"(hi) : "f"(v));
    float h = __uint_as_float(hi);
    float l = v - h;
    asm("cvt.rna.tf32.f32 %0, %1;" : "=r"(lo) : "f"(l));
}

__device__ __forceinline__ void mma8(float* c, const unsigned* a, const unsigned* b) {
    asm volatile(
        "mma.sync.aligned.m16n8k8.row.col.f32.tf32.tf32.f32 "
        "{%0,%1,%2,%3}, {%4,%5,%6,%7}, {%8,%9}, {%0,%1,%2,%3};\n"
        : "+f"(c[0]), "+f"(c[1]), "+f"(c[2]), "+f"(c[3])
        : "r"(a[0]), "r"(a[1]), "r"(a[2]), "r"(a[3]), "r"(b[0]), "r"(b[1]));
}

// shared compute core: assumes As/Bs filled for this k-tile
__device__ __forceinline__ void gemm_tile_compute(
    const float (*As)[BM + 8], const float (*Bs)[BN + 8],
    float acc[4][4][4], int wm, int wn, int gid, int tig) {
#pragma unroll
    for (int ks = 0; ks < 2; ks++) {
        int kb = ks * 8;
        unsigned ah[4][4], al[4][4];
#pragma unroll
        for (int mi = 0; mi < 4; mi++) {
            int mb = wm * 64 + mi * 16;
            split_tf32(As[kb + tig][mb + gid],          ah[mi][0], al[mi][0]);
            split_tf32(As[kb + tig][mb + gid + 8],      ah[mi][1], al[mi][1]);
            split_tf32(As[kb + tig + 4][mb + gid],      ah[mi][2], al[mi][2]);
            split_tf32(As[kb + tig + 4][mb + gid + 8],  ah[mi][3], al[mi][3]);
        }
        unsigned bh[4][2], bl[4][2];
#pragma unroll
        for (int nj = 0; nj < 4; nj++) {
            int nb = wn * 32 + nj * 8;
            split_tf32(Bs[kb + tig][nb + gid],     bh[nj][0], bl[nj][0]);
            split_tf32(Bs[kb + tig + 4][nb + gid], bh[nj][1], bl[nj][1]);
        }
#pragma unroll
        for (int mi = 0; mi < 4; mi++)
#pragma unroll
            for (int nj = 0; nj < 4; nj++) {
                mma8(acc[mi][nj], ah[mi], bh[nj]);
                mma8(acc[mi][nj], ah[mi], bl[nj]);
                mma8(acc[mi][nj], al[mi], bh[nj]);
            }
    }
}

// ---- GEMM1: h[z] = agg[z] @ Wa[z] + ba[z]; fused column stats ----
__global__ __launch_bounds__(256, 1) void k_gemm1(
    const float* __restrict__ Wa, const float* __restrict__ ba,
    int M, int Kd, int Nd) {
    __shared__ float As[BK][BM + 8];
    __shared__ float Bs[BK][BN + 8];
    __shared__ float sS[BN], sQ[BN];
    int z = blockIdx.z;
    const float* A = d_agg[z];
    const float* B = Wa + (long)z * Kd * Nd;
    const float* bias = ba + z * Nd;
    float* C = d_hh[z];

    int tid = threadIdx.x;
    int lane = tid & 31, wid = tid >> 5;
    int wm = wid & 1, wn = wid >> 1;
    int gid = lane >> 2, tig = lane & 3;
    int row0 = blockIdx.y * BM;
    int col0 = blockIdx.x * BN;

    float acc[4][4][4];
#pragma unroll
    for (int a = 0; a < 4; a++)
#pragma unroll
        for (int b = 0; b < 4; b++)
#pragma unroll
            for (int r = 0; r < 4; r++) acc[a][b][r] = 0.f;

    int arow = tid >> 1, akq = (tid & 1) * 8;
    int brow = tid >> 4, bnc = (tid & 15) * 8;

    for (int kt = 0; kt < Kd; kt += BK) {
        {
            int grow = row0 + arow;
            const float* Ap = A + (long)grow * Kd + kt + akq;
#pragma unroll
            for (int j = 0; j < 8; j++) {
                float v = 0.f;
                if (grow < M && (kt + akq + j) < Kd) v = Ap[j];
                As[akq + j][arow] = v;
            }
        }
        {
            int gk = kt + brow;
#pragma unroll
            for (int j = 0; j < 8; j++) {
                float v = 0.f;
                int gn = col0 + bnc + j;
                if (gk < Kd && gn < Nd) v = B[(long)gk * Nd + gn];
                Bs[brow][bnc + j] = v;
            }
        }
        __syncthreads();
        gemm_tile_compute(As, Bs, acc, wm, wn, gid, tig);
        __syncthreads();
    }

    // epilogue: bias add, store, per-column stats
    float colS[8], colQ[8];
#pragma unroll
    for (int i = 0; i < 8; i++) { colS[i] = 0.f; colQ[i] = 0.f; }
#pragma unroll
    for (int mi = 0; mi < 4; mi++)
#pragma unroll
        for (int nj = 0; nj < 4; nj++)
#pragma unroll
            for (int r = 0; r < 4; r++) {
                int row = row0 + wm * 64 + mi * 16 + gid + ((r >> 1) << 3);
                int col = col0 + wn * 32 + nj * 8 + 2 * tig + (r & 1);
                if (row < M && col < Nd) {
                    float v = acc[mi][nj][r] + bias[col];
                    C[(long)row * Nd + col] = v;
                    int ci2 = nj * 2 + (r & 1);
                    colS[ci2] += v;
                    colQ[ci2] += v * v;
                }
            }
    if (tid < BN) { sS[tid] = 0.f; sQ[tid] = 0.f; }
    __syncthreads();
#pragma unroll
    for (int i = 0; i < 8; i++) {
        int lc = wn * 32 + (i >> 1) * 8 + 2 * tig + (i & 1);
        atomicAdd(&sS[lc], colS[i]);
        atomicAdd(&sQ[lc], colQ[i]);
    }
    __syncthreads();
    if (tid < BN) {
        int c = col0 + tid;
        if (c < Nd) {
            atomicAdd(&d_cs[z * 512 + c], sS[tid]);
            atomicAdd(&d_css[z * 512 + c], sQ[tid]);
        }
    }
}

// ---- GEMM2: dest = sum_z relu(BN(h[z])) @ Wb[z] + sum_z bb[z] ----
__global__ __launch_bounds__(256, 1) void k_gemm2(
    const float* __restrict__ Wb, const float* __restrict__ bb,
    float* __restrict__ C, int M, int Kd, int Nd) {
    __shared__ float As[BK][BM + 8];
    __shared__ float Bs[BK][BN + 8];

    int tid = threadIdx.x;
    int lane = tid & 31, wid = tid >> 5;
    int wm = wid & 1, wn = wid >> 1;
    int gid = lane >> 2, tig = lane & 3;
    int row0 = blockIdx.y * BM;
    int col0 = blockIdx.x * BN;

    float acc[4][4][4];
#pragma unroll
    for (int a = 0; a < 4; a++)
#pragma unroll
        for (int b = 0; b < 4; b++)
#pragma unroll
            for (int r = 0; r < 4; r++) acc[a][b][r] = 0.f;

    int arow = tid >> 1, akq = (tid & 1) * 8;
    int brow = tid >> 4, bnc = (tid & 15) * 8;

    for (int z = 0; z < KT; z++) {
        const float* A = d_hh[z];
        const float* B = Wb + (long)z * Kd * Nd;
        const float* sc = &d_scale[z * 512];
        const float* sh = &d_shift[z * 512];
        for (int kt = 0; kt < Kd; kt += BK) {
            {
                int grow = row0 + arow;
                const float* Ap = A + (long)grow * Kd + kt + akq;
#pragma unroll
                for (int j = 0; j < 8; j++) {
                    float v = 0.f;
                    int ck = kt + akq + j;
                    if (grow < M && ck < Kd) {
                        v = Ap[j];
                        v = fmaxf(fmaf(v, sc[ck], sh[ck]), 0.f);  // fused BN+ReLU
                    }
                    As[akq + j][arow] = v;
                }
            }
            {
                int gk = kt + brow;
#pragma unroll
                for (int j = 0; j < 8; j++) {
                    float v = 0.f;
                    int gn = col0 + bnc + j;
                    if (gk < Kd && gn < Nd) v = B[(long)gk * Nd + gn];
                    Bs[brow][bnc + j] = v;
                }
            }
            __syncthreads();
            gemm_tile_compute(As, Bs, acc, wm, wn, gid, tig);
            __syncthreads();
        }
    }

#pragma unroll
    for (int mi = 0; mi < 4; mi++)
#pragma unroll
        for (int nj = 0; nj < 4; nj++)
#pragma unroll
            for (int r = 0; r < 4; r++) {
                int row = row0 + wm * 64 + mi * 16 + gid + ((r >> 1) << 3);
                int col = col0 + wn * 32 + nj * 8 + 2 * tig + (r & 1);
                if (row < M && col < Nd) {
                    float bsum = bb[col] + bb[Nd + col] + bb[2 * Nd + col];
                    C[(long)row * Nd + col] = acc[mi][nj][r] + bsum;
                }
            }
}

// ---------------- small kernels ----------------
__global__ void k_zstat() {
    int i = blockIdx.x * blockDim.x + threadIdx.x;
    if (i < KT * 512) { d_cs[i] = 0.f; d_css[i] = 0.f; }
}

__global__ void k_bnfinal(const float* __restrict__ gB,
                          const float* __restrict__ btB, int C) {
    int k = blockIdx.x;
    int c = threadIdx.x;
    if (c >= C) return;
    float mu  = d_cs[k * 512 + c] / (float)NN;
    float var = d_css[k * 512 + c] / (float)NN - mu * mu;
    var = fmaxf(var, 0.f);
    float s = gB[k * C + c] * rsqrtf(var + BN_EPS);
    d_scale[k * 512 + c] = s;
    d_shift[k * 512 + c] = btB[k * C + c] - mu * s;
}

__global__ void k_leaky() {
    int i = blockIdx.x * blockDim.x + threadIdx.x;
    if (i >= NN * 256) return;
    float v = d_accb[i];
    d_xcur[i] = (v > 0.f) ? v : 0.01f * v;
}

// ---------------- launch ----------------
extern "C" void kernel_launch(void* const* d_in, const int* in_sizes, int n_in,
                              void* d_out, int out_size) {
    // GB300 ATS pitfall: host-shadow addresses of __device__ symbols are
    // silently usable by the GPU — always resolve real device addresses.
    float *p_acc, *p_xcur;
    cudaGetSymbolAddress((void**)&p_acc,  d_accb);
    cudaGetSymbolAddress((void**)&p_xcur, d_xcur);

    const float* x  = (const float*)d_in[0];
    const int*   ei = (const int*)d_in[1];
    const float* ea = (const float*)d_in[2];

    const int ciL[3] = {170, 256, 256};
    const int chL[3] = {340, 512, 512};
    const int co = 256;

    k_zero_counts<<<(KT * NN + 255) / 256, 256>>>();
    k_count<<<(KT * NE + 255) / 256, 256>>>(ei);
    k_scan<<<KT, 1024>>>();
    k_fill<<<(KT * NE + 255) / 256, 256>>>(ei);

    const float* xin = x;
    for (int l = 0; l < 3; l++) {
        int ci = ciL[l], ch = chL[l];
        const float* We = (const float*)d_in[3 + l * 8 + 0];
        const float* be = (const float*)d_in[3 + l * 8 + 1];
        const float* Wa = (const float*)d_in[3 + l * 8 + 2];
        const float* ba = (const float*)d_in[3 + l * 8 + 3];
        const float* g  = (const float*)d_in[3 + l * 8 + 4];
        const float* bt = (const float*)d_in[3 + l * 8 + 5];
        const float* Wb = (const float*)d_in[3 + l * 8 + 6];
        const float* bb = (const float*)d_in[3 + l * 8 + 7];
        float* dest = (l == 2) ? (float*)d_out : p_acc;

        dim3 ga(NN, KT);
        k_aggr<<<ga, 256>>>(xin, ei, ea, We, be, ci);

        k_zstat<<<6, 256>>>();

        dim3 g1((ch + BN - 1) / BN, (NN + BM - 1) / BM, KT);
        k_gemm1<<<g1, 256>>>(Wa, ba, NN, ci, ch);

        k_bnfinal<<<KT, 512>>>(g, bt, ch);

        dim3 g2((co + BN - 1) / BN, (NN + BM - 1) / BM);
        k_gemm2<<<g2, 256>>>(Wb, bb, dest, NN, ch, co);

        if (l < 2) {
            k_leaky<<<(NN * 256 + 255) / 256, 256>>>();
            xin = p_xcur;
        }
    }
}

// round 9
// speedup vs baseline: 1.2722x; 1.2722x over previous
#include <cuda_runtime.h>
#include <cuda_bf16.h>

#define NN 16500
#define NE 100000
#define KT 3
#define GEN_EPS 1e-7f
#define BN_EPS 1e-5f

// ---------------- scratch ----------------
__device__ int   d_cnt[KT][NN];
__device__ int   d_off[KT][NN + 1];
__device__ int   d_cur[KT][NN];
__device__ int   d_eid[KT][NE];
__device__ float d_agg[KT][NN * 256];
__device__ float d_hh[KT][NN * 512];
__device__ float d_xcur[NN * 256];
__device__ float d_cs[KT * 512], d_css[KT * 512];
__device__ float d_scale[KT * 512], d_shift[KT * 512];

// ---------------- CSR build ----------------
__global__ void k_zero_counts() {
    int i = blockIdx.x * blockDim.x + threadIdx.x;
    if (i < KT * NN) ((int*)d_cnt)[i] = 0;
}

__global__ void k_count(const int* __restrict__ ei) {
    int i = blockIdx.x * blockDim.x + threadIdx.x;
    if (i >= KT * NE) return;
    int k = i / NE, e = i % NE;
    atomicAdd(&d_cnt[k][ei[k * 2 * NE + NE + e]], 1);
}

__global__ void k_scan() {
    __shared__ int sh[1024];
    int k = blockIdx.x, tid = threadIdx.x;
    int carry = 0;
    if (tid == 0) d_off[k][0] = 0;
    for (int base = 0; base < NN; base += 1024) {
        int i = base + tid;
        int v = (i < NN) ? d_cnt[k][i] : 0;
        sh[tid] = v;
        __syncthreads();
        for (int o = 1; o < 1024; o <<= 1) {
            int t = (tid >= o) ? sh[tid - o] : 0;
            __syncthreads();
            sh[tid] += t;
            __syncthreads();
        }
        int inc = sh[tid];
        int tot = sh[1023];
        if (i < NN) {
            d_off[k][i + 1] = carry + inc;
            d_cur[k][i]     = carry + inc - v;
        }
        __syncthreads();
        carry += tot;
    }
}

__global__ void k_fill(const int* __restrict__ ei) {
    int i = blockIdx.x * blockDim.x + threadIdx.x;
    if (i >= KT * NE) return;
    int k = i / NE, e = i % NE;
    int pos = atomicAdd(&d_cur[k][ei[k * 2 * NE + NE + e]], 1);
    d_eid[k][pos] = e;
}

// --------- batched GENConv aggregation (online softmax, ONE exp/edge) --------
__global__ void k_aggr(const float* __restrict__ xin,
                       const int* __restrict__ ei,
                       const float* __restrict__ ea,
                       const float* __restrict__ WeB,
                       const float* __restrict__ beB,
                       int ci) {
    int n = blockIdx.x;
    int k = blockIdx.y;
    int c = threadIdx.x;
    if (c >= ci) return;
    const int*   src = ei + k * 2 * NE;
    const float* eak = ea + k * NE;
    float we = WeB[k * ci + c], bec = beB[k * ci + c];
    float xn = xin[n * ci + c];
    float v = fmaxf(xn + we + bec, 0.f) + GEN_EPS;  // self loop (ea = 1)
    float m = v, den = 1.f, ws = v;
    int j0 = d_off[k][n], j1 = d_off[k][n + 1];
    for (int j = j0; j < j1; j++) {
        int e = d_eid[k][j];
        int s = src[e];
        float a = eak[e];
        float u = fmaxf(xin[s * ci + c] + a * we + bec, 0.f) + GEN_EPS;
        float nm = fmaxf(m, u);
        float e1 = __expf(fminf(m, u) - nm);   // single exp
        if (u > m) { den = den * e1 + 1.f; ws = ws * e1 + u; }
        else       { den = den + e1;       ws = ws + u * e1; }
        m = nm;
    }
    d_agg[k][n * ci + c] = ws / den + xn;
}

// ---------------- bf16 split-2 tensor-core GEMM machinery ----------------
#define BM 128
#define BN 128
#define BK 32
#define BKP 40   // padded k-stride (bf16 elems): conflict-free fragment loads

__device__ __forceinline__ void mma_bf16(float* c, const unsigned* a,
                                         const unsigned* b) {
    asm volatile(
        "mma.sync.aligned.m16n8k16.row.col.f32.bf16.bf16.f32 "
        "{%0,%1,%2,%3}, {%4,%5,%6,%7}, {%8,%9}, {%0,%1,%2,%3};\n"
        : "+f"(c[0]), "+f"(c[1]), "+f"(c[2]), "+f"(c[3])
        : "r"(a[0]), "r"(a[1]), "r"(a[2]), "r"(a[3]), "r"(b[0]), "r"(b[1]));
}

__device__ __forceinline__ void split_bf16(float v, __nv_bfloat16& hi,
                                           __nv_bfloat16& lo) {
    hi = __float2bfloat16(v);
    lo = __float2bfloat16(v - __bfloat162float(hi));
}

// core: compute one BK-slab from prefilled hi/lo tiles
__device__ __forceinline__ void mma_slab(
    const __nv_bfloat16 (*Ah)[BKP], const __nv_bfloat16 (*Al)[BKP],
    const __nv_bfloat16 (*Bh)[BKP], const __nv_bfloat16 (*Bl)[BKP],
    float acc[4][4][4], int wm, int wn, int gid, int tig) {
#pragma unroll
    for (int ks = 0; ks < 2; ks++) {
        int kb = ks * 16 + 2 * tig;
        unsigned bh[4][2], bl[4][2];
#pragma unroll
        for (int nj = 0; nj < 4; nj++) {
            int nn2 = wn * 32 + nj * 8 + gid;
            bh[nj][0] = *(const unsigned*)&Bh[nn2][kb];
            bh[nj][1] = *(const unsigned*)&Bh[nn2][kb + 8];
            bl[nj][0] = *(const unsigned*)&Bl[nn2][kb];
            bl[nj][1] = *(const unsigned*)&Bl[nn2][kb + 8];
        }
#pragma unroll
        for (int mi = 0; mi < 4; mi++) {
            int r0 = wm * 64 + mi * 16 + gid;
            unsigned ah[4], al[4];
            ah[0] = *(const unsigned*)&Ah[r0][kb];
            ah[1] = *(const unsigned*)&Ah[r0 + 8][kb];
            ah[2] = *(const unsigned*)&Ah[r0][kb + 8];
            ah[3] = *(const unsigned*)&Ah[r0 + 8][kb + 8];
            al[0] = *(const unsigned*)&Al[r0][kb];
            al[1] = *(const unsigned*)&Al[r0 + 8][kb];
            al[2] = *(const unsigned*)&Al[r0][kb + 8];
            al[3] = *(const unsigned*)&Al[r0 + 8][kb + 8];
#pragma unroll
            for (int nj = 0; nj < 4; nj++) {
                mma_bf16(acc[mi][nj], ah, bh[nj]);
                mma_bf16(acc[mi][nj], ah, bl[nj]);
                mma_bf16(acc[mi][nj], al, bh[nj]);
            }
        }
    }
}

// fill B tile transposed: Bs[n][k] from B[k][n], split hi/lo
__device__ __forceinline__ void fill_B(
    const float* __restrict__ B, int kt, int col0, int Kd, int Nd,
    __nv_bfloat16 (*Bh)[BKP], __nv_bfloat16 (*Bl)[BKP], int tid) {
    int n = tid & 127;
    int kh = (tid >> 7) * 16;
    int gn = col0 + n;
#pragma unroll
    for (int j = 0; j < 16; j++) {
        int gk = kt + kh + j;
        float v = 0.f;
        if (gk < Kd && gn < Nd) v = B[(long)gk * Nd + gn];
        split_bf16(v, Bh[n][kh + j], Bl[n][kh + j]);
    }
}

// ---- GEMM1: h[z] = agg[z] @ Wa[z] + ba[z]; fused column stats ----
__global__ __launch_bounds__(256, 1) void k_gemm1(
    const float* __restrict__ Wa, const float* __restrict__ ba,
    int M, int Kd, int Nd) {
    __shared__ __align__(16) __nv_bfloat16 Ah[BM][BKP], Al[BM][BKP];
    __shared__ __align__(16) __nv_bfloat16 Bh[BN][BKP], Bl[BN][BKP];
    __shared__ float sS[BN], sQ[BN];
    int z = blockIdx.z;
    const float* A = d_agg[z];
    const float* B = Wa + (long)z * Kd * Nd;
    const float* bias = ba + z * Nd;
    float* C = d_hh[z];

    int tid = threadIdx.x;
    int lane = tid & 31, wid = tid >> 5;
    int wm = wid & 1, wn = wid >> 1;
    int gid = lane >> 2, tig = lane & 3;
    int row0 = blockIdx.y * BM;
    int col0 = blockIdx.x * BN;

    float acc[4][4][4];
#pragma unroll
    for (int a = 0; a < 4; a++)
#pragma unroll
        for (int b = 0; b < 4; b++)
#pragma unroll
            for (int r = 0; r < 4; r++) acc[a][b][r] = 0.f;

    int arow = tid >> 1, akq = (tid & 1) * 16;
    int grow = row0 + arow;

    for (int kt = 0; kt < Kd; kt += BK) {
#pragma unroll
        for (int j = 0; j < 16; j++) {
            int ck = kt + akq + j;
            float v = 0.f;
            if (grow < M && ck < Kd) v = A[(long)grow * Kd + ck];
            split_bf16(v, Ah[arow][akq + j], Al[arow][akq + j]);
        }
        fill_B(B, kt, col0, Kd, Nd, Bh, Bl, tid);
        __syncthreads();
        mma_slab(Ah, Al, Bh, Bl, acc, wm, wn, gid, tig);
        __syncthreads();
    }

    float colS[8], colQ[8];
#pragma unroll
    for (int i = 0; i < 8; i++) { colS[i] = 0.f; colQ[i] = 0.f; }
#pragma unroll
    for (int mi = 0; mi < 4; mi++)
#pragma unroll
        for (int nj = 0; nj < 4; nj++)
#pragma unroll
            for (int r = 0; r < 4; r++) {
                int row = row0 + wm * 64 + mi * 16 + gid + ((r >> 1) << 3);
                int col = col0 + wn * 32 + nj * 8 + 2 * tig + (r & 1);
                if (row < M && col < Nd) {
                    float v = acc[mi][nj][r] + bias[col];
                    C[(long)row * Nd + col] = v;
                    int ci2 = nj * 2 + (r & 1);
                    colS[ci2] += v;
                    colQ[ci2] += v * v;
                }
            }
    if (tid < BN) { sS[tid] = 0.f; sQ[tid] = 0.f; }
    __syncthreads();
#pragma unroll
    for (int i = 0; i < 8; i++) {
        int lc = wn * 32 + (i >> 1) * 8 + 2 * tig + (i & 1);
        atomicAdd(&sS[lc], colS[i]);
        atomicAdd(&sQ[lc], colQ[i]);
    }
    __syncthreads();
    if (tid < BN) {
        int c = col0 + tid;
        if (c < Nd) {
            atomicAdd(&d_cs[z * 512 + c], sS[tid]);
            atomicAdd(&d_css[z * 512 + c], sQ[tid]);
        }
    }
}

// ---- GEMM2: dest = act( sum_z relu(BN(h[z])) @ Wb[z] + sum_z bb[z] ) ----
__global__ __launch_bounds__(256, 1) void k_gemm2(
    const float* __restrict__ Wb, const float* __restrict__ bb,
    float* __restrict__ C, int M, int Kd, int Nd, int leaky) {
    __shared__ __align__(16) __nv_bfloat16 Ah[BM][BKP], Al[BM][BKP];
    __shared__ __align__(16) __nv_bfloat16 Bh[BN][BKP], Bl[BN][BKP];

    int tid = threadIdx.x;
    int lane = tid & 31, wid = tid >> 5;
    int wm = wid & 1, wn = wid >> 1;
    int gid = lane >> 2, tig = lane & 3;
    int row0 = blockIdx.y * BM;
    int col0 = blockIdx.x * BN;

    float acc[4][4][4];
#pragma unroll
    for (int a = 0; a < 4; a++)
#pragma unroll
        for (int b = 0; b < 4; b++)
#pragma unroll
            for (int r = 0; r < 4; r++) acc[a][b][r] = 0.f;

    int arow = tid >> 1, akq = (tid & 1) * 16;
    int grow = row0 + arow;

    for (int z = 0; z < KT; z++) {
        const float* A = d_hh[z];
        const float* B = Wb + (long)z * Kd * Nd;
        const float* sc = &d_scale[z * 512];
        const float* sh = &d_shift[z * 512];
        for (int kt = 0; kt < Kd; kt += BK) {
#pragma unroll
            for (int j = 0; j < 16; j++) {
                int ck = kt + akq + j;
                float v = 0.f;
                if (grow < M && ck < Kd) {
                    v = A[(long)grow * Kd + ck];
                    v = fmaxf(fmaf(v, sc[ck], sh[ck]), 0.f);  // fused BN+ReLU
                }
                split_bf16(v, Ah[arow][akq + j], Al[arow][akq + j]);
            }
            fill_B(B, kt, col0, Kd, Nd, Bh, Bl, tid);
            __syncthreads();
            mma_slab(Ah, Al, Bh, Bl, acc, wm, wn, gid, tig);
            __syncthreads();
        }
    }

#pragma unroll
    for (int mi = 0; mi < 4; mi++)
#pragma unroll
        for (int nj = 0; nj < 4; nj++)
#pragma unroll
            for (int r = 0; r < 4; r++) {
                int row = row0 + wm * 64 + mi * 16 + gid + ((r >> 1) << 3);
                int col = col0 + wn * 32 + nj * 8 + 2 * tig + (r & 1);
                if (row < M && col < Nd) {
                    float v = acc[mi][nj][r] + bb[col] + bb[Nd + col] +
                              bb[2 * Nd + col];
                    if (leaky) v = (v > 0.f) ? v : 0.01f * v;
                    C[(long)row * Nd + col] = v;
                }
            }
}

// ---------------- small kernels ----------------
__global__ void k_zstat() {
    int i = blockIdx.x * blockDim.x + threadIdx.x;
    if (i < KT * 512) { d_cs[i] = 0.f; d_css[i] = 0.f; }
}

__global__ void k_bnfinal(const float* __restrict__ gB,
                          const float* __restrict__ btB, int C) {
    int k = blockIdx.x;
    int c = threadIdx.x;
    if (c >= C) return;
    float mu  = d_cs[k * 512 + c] / (float)NN;
    float var = d_css[k * 512 + c] / (float)NN - mu * mu;
    var = fmaxf(var, 0.f);
    float s = gB[k * C + c] * rsqrtf(var + BN_EPS);
    d_scale[k * 512 + c] = s;
    d_shift[k * 512 + c] = btB[k * C + c] - mu * s;
}

// ---------------- launch ----------------
extern "C" void kernel_launch(void* const* d_in, const int* in_sizes, int n_in,
                              void* d_out, int out_size) {
    // GB300 ATS pitfall: resolve REAL device addresses of __device__ symbols.
    float* p_xcur;
    cudaGetSymbolAddress((void**)&p_xcur, d_xcur);

    const float* x  = (const float*)d_in[0];
    const int*   ei = (const int*)d_in[1];
    const float* ea = (const float*)d_in[2];

    const int ciL[3] = {170, 256, 256};
    const int chL[3] = {340, 512, 512};
    const int co = 256;

    k_zero_counts<<<(KT * NN + 255) / 256, 256>>>();
    k_count<<<(KT * NE + 255) / 256, 256>>>(ei);
    k_scan<<<KT, 1024>>>();
    k_fill<<<(KT * NE + 255) / 256, 256>>>(ei);

    const float* xin = x;
    for (int l = 0; l < 3; l++) {
        int ci = ciL[l], ch = chL[l];
        const float* We = (const float*)d_in[3 + l * 8 + 0];
        const float* be = (const float*)d_in[3 + l * 8 + 1];
        const float* Wa = (const float*)d_in[3 + l * 8 + 2];
        const float* ba = (const float*)d_in[3 + l * 8 + 3];
        const float* g  = (const float*)d_in[3 + l * 8 + 4];
        const float* bt = (const float*)d_in[3 + l * 8 + 5];
        const float* Wb = (const float*)d_in[3 + l * 8 + 6];
        const float* bb = (const float*)d_in[3 + l * 8 + 7];
        float* dest = (l == 2) ? (float*)d_out : p_xcur;

        dim3 ga(NN, KT);
        k_aggr<<<ga, 256>>>(xin, ei, ea, We, be, ci);

        k_zstat<<<6, 256>>>();

        dim3 g1((ch + BN - 1) / BN, (NN + BM - 1) / BM, KT);
        k_gemm1<<<g1, 256>>>(Wa, ba, NN, ci, ch);

        k_bnfinal<<<KT, 512>>>(g, bt, ch);

        dim3 g2((co + BN - 1) / BN, (NN + BM - 1) / BM);
        k_gemm2<<<g2, 256>>>(Wb, bb, dest, NN, ch, co, (l < 2) ? 1 : 0);

        if (l < 2) xin = p_xcur;
    }
}

// round 10
// speedup vs baseline: 1.5180x; 1.1932x over previous
#include <cuda_runtime.h>
#include <cuda_bf16.h>

#define NN 16500
#define NE 100000
#define KT 3
#define GEN_EPS 1e-7f
#define BN_EPS 1e-5f

// ---------------- scratch ----------------
__device__ int   d_cnt[KT][NN];          // static zero-init; re-zeroed by k_fill
__device__ int   d_off[KT][NN + 1];
__device__ int   d_cur[KT][NN];
__device__ int   d_eid[KT][NE];
__device__ float d_agg[KT][NN * 256];
__device__ float d_hh[KT][NN * 512];
__device__ float d_xcur[NN * 256];
__device__ float d_cs[KT * 512], d_css[KT * 512];
__device__ float d_scale[KT * 512], d_shift[KT * 512];

// ---------------- CSR build ----------------
__global__ void k_count(const int* __restrict__ ei) {
    int i = blockIdx.x * blockDim.x + threadIdx.x;
    if (i >= KT * NE) return;
    int k = i / NE, e = i % NE;
    atomicAdd(&d_cnt[k][ei[k * 2 * NE + NE + e]], 1);
}

__global__ void k_scan() {
    __shared__ int sh[1024];
    int k = blockIdx.x, tid = threadIdx.x;
    int carry = 0;
    if (tid == 0) d_off[k][0] = 0;
    for (int base = 0; base < NN; base += 1024) {
        int i = base + tid;
        int v = (i < NN) ? d_cnt[k][i] : 0;
        sh[tid] = v;
        __syncthreads();
        for (int o = 1; o < 1024; o <<= 1) {
            int t = (tid >= o) ? sh[tid - o] : 0;
            __syncthreads();
            sh[tid] += t;
            __syncthreads();
        }
        int inc = sh[tid];
        int tot = sh[1023];
        if (i < NN) {
            d_off[k][i + 1] = carry + inc;
            d_cur[k][i]     = carry + inc - v;
        }
        __syncthreads();
        carry += tot;
    }
}

__global__ void k_fill(const int* __restrict__ ei) {
    int i = blockIdx.x * blockDim.x + threadIdx.x;
    if (i < KT * NE) {
        int k = i / NE, e = i % NE;
        int pos = atomicAdd(&d_cur[k][ei[k * 2 * NE + NE + e]], 1);
        d_eid[k][pos] = e;
    }
    // re-zero d_cnt for the NEXT kernel_launch call (nothing reads it until
    // next call's k_count; first call relies on static zero-init).
    if (i < KT * NN) ((int*)d_cnt)[i] = 0;
}

// --------- batched GENConv aggregation: smem edge cache + 2-wide merge -------
__global__ void k_aggr(const float* __restrict__ xin,
                       const int* __restrict__ ei,
                       const float* __restrict__ ea,
                       const float* __restrict__ WeB,
                       const float* __restrict__ beB,
                       int ci) {
    __shared__ int   s_src[192];
    __shared__ float s_a[192];
    int n = blockIdx.x, k = blockIdx.y;
    int tid = threadIdx.x;

    // fold BN-stat zeroing in (runs before k_gemm1's atomics)
    if (n == 0) {
        for (int i = tid; i < 512; i += blockDim.x) {
            d_cs[k * 512 + i] = 0.f;
            d_css[k * 512 + i] = 0.f;
        }
    }

    int j0  = d_off[k][n];
    int deg = d_off[k][n + 1] - j0;
    int cap = min(deg, 192);
    const int*   src = ei + k * 2 * NE;
    const float* eak = ea + k * NE;
    for (int j = tid; j < cap; j += blockDim.x) {
        int e = d_eid[k][j0 + j];
        s_src[j] = src[e];
        s_a[j]   = eak[e];
    }
    __syncthreads();

    int c = tid;
    if (c >= ci) return;
    float we = WeB[k * ci + c], bec = beB[k * ci + c];
    float xn = xin[n * ci + c];
    float v = fmaxf(xn + we + bec, 0.f) + GEN_EPS;   // self loop (ea = 1)
    float m = v, den = 1.f, ws = v;

    int j = 0;
    for (; j + 2 <= cap; j += 2) {   // two independent loads per step (MLP=2)
        int   s1 = s_src[j],  s2 = s_src[j + 1];
        float a1 = s_a[j],    a2 = s_a[j + 1];
        float x1 = xin[s1 * ci + c];
        float x2 = xin[s2 * ci + c];
        float u1 = fmaxf(x1 + a1 * we + bec, 0.f) + GEN_EPS;
        float u2 = fmaxf(x2 + a2 * we + bec, 0.f) + GEN_EPS;
        float mm = fmaxf(u1, u2);
        float e2 = __expf(fminf(u1, u2) - mm);
        float den2 = 1.f + e2;
        float ws2  = (u1 >= u2) ? fmaf(u2, e2, u1) : fmaf(u1, e2, u2);
        float nm = fmaxf(m, mm);
        float e3 = __expf(fminf(m, mm) - nm);
        if (mm > m) { den = fmaf(den, e3, den2); ws = fmaf(ws, e3, ws2); }
        else        { den = fmaf(den2, e3, den); ws = fmaf(ws2, e3, ws); }
        m = nm;
    }
    for (; j < cap; j++) {
        int s = s_src[j];
        float u = fmaxf(xin[s * ci + c] + s_a[j] * we + bec, 0.f) + GEN_EPS;
        float nm = fmaxf(m, u);
        float e1 = __expf(fminf(m, u) - nm);
        if (u > m) { den = fmaf(den, e1, 1.f); ws = fmaf(ws, e1, u); }
        else       { den = den + e1;           ws = fmaf(u, e1, ws); }
        m = nm;
    }
    for (int jj = cap; jj < deg; jj++) {  // overflow tail (deg>192: ~never)
        int e = d_eid[k][j0 + jj];
        int s = src[e];
        float u = fmaxf(xin[s * ci + c] + eak[e] * we + bec, 0.f) + GEN_EPS;
        float nm = fmaxf(m, u);
        float e1 = __expf(fminf(m, u) - nm);
        if (u > m) { den = fmaf(den, e1, 1.f); ws = fmaf(ws, e1, u); }
        else       { den = den + e1;           ws = fmaf(u, e1, ws); }
        m = nm;
    }
    d_agg[k][n * ci + c] = ws / den + xn;
}

// ---------------- bf16 split-2 tensor-core GEMM machinery ----------------
#define BM 128
#define BN 128
#define BK 32
#define BKP 40

__device__ __forceinline__ void mma_bf16(float* c, const unsigned* a,
                                         const unsigned* b) {
    asm volatile(
        "mma.sync.aligned.m16n8k16.row.col.f32.bf16.bf16.f32 "
        "{%0,%1,%2,%3}, {%4,%5,%6,%7}, {%8,%9}, {%0,%1,%2,%3};\n"
        : "+f"(c[0]), "+f"(c[1]), "+f"(c[2]), "+f"(c[3])
        : "r"(a[0]), "r"(a[1]), "r"(a[2]), "r"(a[3]), "r"(b[0]), "r"(b[1]));
}

__device__ __forceinline__ void split_bf16(float v, __nv_bfloat16& hi,
                                           __nv_bfloat16& lo) {
    hi = __float2bfloat16(v);
    lo = __float2bfloat16(v - __bfloat162float(hi));
}

__device__ __forceinline__ void mma_slab(
    const __nv_bfloat16 (*Ah)[BKP], const __nv_bfloat16 (*Al)[BKP],
    const __nv_bfloat16 (*Bh)[BKP], const __nv_bfloat16 (*Bl)[BKP],
    float acc[4][4][4], int wm, int wn, int gid, int tig) {
#pragma unroll
    for (int ks = 0; ks < 2; ks++) {
        int kb = ks * 16 + 2 * tig;
        unsigned bh[4][2], bl[4][2];
#pragma unroll
        for (int nj = 0; nj < 4; nj++) {
            int nn2 = wn * 32 + nj * 8 + gid;
            bh[nj][0] = *(const unsigned*)&Bh[nn2][kb];
            bh[nj][1] = *(const unsigned*)&Bh[nn2][kb + 8];
            bl[nj][0] = *(const unsigned*)&Bl[nn2][kb];
            bl[nj][1] = *(const unsigned*)&Bl[nn2][kb + 8];
        }
#pragma unroll
        for (int mi = 0; mi < 4; mi++) {
            int r0 = wm * 64 + mi * 16 + gid;
            unsigned ah[4], al[4];
            ah[0] = *(const unsigned*)&Ah[r0][kb];
            ah[1] = *(const unsigned*)&Ah[r0 + 8][kb];
            ah[2] = *(const unsigned*)&Ah[r0][kb + 8];
            ah[3] = *(const unsigned*)&Ah[r0 + 8][kb + 8];
            al[0] = *(const unsigned*)&Al[r0][kb];
            al[1] = *(const unsigned*)&Al[r0 + 8][kb];
            al[2] = *(const unsigned*)&Al[r0][kb + 8];
            al[3] = *(const unsigned*)&Al[r0 + 8][kb + 8];
#pragma unroll
            for (int nj = 0; nj < 4; nj++) {
                mma_bf16(acc[mi][nj], ah, bh[nj]);
                mma_bf16(acc[mi][nj], ah, bl[nj]);
                mma_bf16(acc[mi][nj], al, bh[nj]);
            }
        }
    }
}

// ---- GEMM1: h[z] = agg[z] @ Wa[z] + ba[z]; fused stats; reg double-buffer ----
__global__ __launch_bounds__(256) void k_gemm1(
    const float* __restrict__ Wa, const float* __restrict__ ba,
    int M, int Kd, int Nd) {
    __shared__ __align__(16) __nv_bfloat16 Ah[BM][BKP], Al[BM][BKP];
    __shared__ __align__(16) __nv_bfloat16 Bh[BN][BKP], Bl[BN][BKP];
    __shared__ float sS[BN], sQ[BN];
    int z = blockIdx.z;
    const float* A = d_agg[z];
    const float* B = Wa + (long)z * Kd * Nd;
    const float* bias = ba + z * Nd;
    float* C = d_hh[z];

    int tid = threadIdx.x;
    int lane = tid & 31, wid = tid >> 5;
    int wm = wid & 1, wn = wid >> 1;
    int gid = lane >> 2, tig = lane & 3;
    int row0 = blockIdx.y * BM;
    int col0 = blockIdx.x * BN;

    float acc[4][4][4];
#pragma unroll
    for (int a = 0; a < 4; a++)
#pragma unroll
        for (int b = 0; b < 4; b++)
#pragma unroll
            for (int r = 0; r < 4; r++) acc[a][b][r] = 0.f;

    int arow = tid >> 1, akq = (tid & 1) * 16;
    int grow = row0 + arow;
    int bn_ = tid & 127, bkh = (tid >> 7) * 16;
    int gn = col0 + bn_;

    float aR[16], bR[16];
    auto loadT = [&](int kt) {
#pragma unroll
        for (int jj = 0; jj < 16; jj++) {
            int ck = kt + akq + jj;
            aR[jj] = (grow < M && ck < Kd) ? A[(long)grow * Kd + ck] : 0.f;
        }
#pragma unroll
        for (int jj = 0; jj < 16; jj++) {
            int gk = kt + bkh + jj;
            bR[jj] = (gk < Kd && gn < Nd) ? B[(long)gk * Nd + gn] : 0.f;
        }
    };

    int nk = (Kd + BK - 1) / BK;
    loadT(0);
    for (int t = 0; t < nk; t++) {
#pragma unroll
        for (int jj = 0; jj < 16; jj++)
            split_bf16(aR[jj], Ah[arow][akq + jj], Al[arow][akq + jj]);
#pragma unroll
        for (int jj = 0; jj < 16; jj++)
            split_bf16(bR[jj], Bh[bn_][bkh + jj], Bl[bn_][bkh + jj]);
        __syncthreads();
        if (t + 1 < nk) loadT((t + 1) * BK);   // prefetch hides under MMAs
        mma_slab(Ah, Al, Bh, Bl, acc, wm, wn, gid, tig);
        __syncthreads();
    }

    float colS[8], colQ[8];
#pragma unroll
    for (int i = 0; i < 8; i++) { colS[i] = 0.f; colQ[i] = 0.f; }
#pragma unroll
    for (int mi = 0; mi < 4; mi++)
#pragma unroll
        for (int nj = 0; nj < 4; nj++)
#pragma unroll
            for (int r = 0; r < 4; r++) {
                int row = row0 + wm * 64 + mi * 16 + gid + ((r >> 1) << 3);
                int col = col0 + wn * 32 + nj * 8 + 2 * tig + (r & 1);
                if (row < M && col < Nd) {
                    float vv = acc[mi][nj][r] + bias[col];
                    C[(long)row * Nd + col] = vv;
                    int ci2 = nj * 2 + (r & 1);
                    colS[ci2] += vv;
                    colQ[ci2] += vv * vv;
                }
            }
    if (tid < BN) { sS[tid] = 0.f; sQ[tid] = 0.f; }
    __syncthreads();
#pragma unroll
    for (int i = 0; i < 8; i++) {
        int lc = wn * 32 + (i >> 1) * 8 + 2 * tig + (i & 1);
        atomicAdd(&sS[lc], colS[i]);
        atomicAdd(&sQ[lc], colQ[i]);
    }
    __syncthreads();
    if (tid < BN) {
        int c = col0 + tid;
        if (c < Nd) {
            atomicAdd(&d_cs[z * 512 + c], sS[tid]);
            atomicAdd(&d_css[z * 512 + c], sQ[tid]);
        }
    }
}

// ---- GEMM2: dest = act( sum_z relu(BN(h[z])) @ Wb[z] + sum bb ) ----
__global__ __launch_bounds__(256) void k_gemm2(
    const float* __restrict__ Wb, const float* __restrict__ bb,
    float* __restrict__ C, int M, int Kd, int Nd, int leaky) {
    __shared__ __align__(16) __nv_bfloat16 Ah[BM][BKP], Al[BM][BKP];
    __shared__ __align__(16) __nv_bfloat16 Bh[BN][BKP], Bl[BN][BKP];

    int tid = threadIdx.x;
    int lane = tid & 31, wid = tid >> 5;
    int wm = wid & 1, wn = wid >> 1;
    int gid = lane >> 2, tig = lane & 3;
    int row0 = blockIdx.y * BM;
    int col0 = blockIdx.x * BN;

    float acc[4][4][4];
#pragma unroll
    for (int a = 0; a < 4; a++)
#pragma unroll
        for (int b = 0; b < 4; b++)
#pragma unroll
            for (int r = 0; r < 4; r++) acc[a][b][r] = 0.f;

    int arow = tid >> 1, akq = (tid & 1) * 16;
    int grow = row0 + arow;
    int bn_ = tid & 127, bkh = (tid >> 7) * 16;
    int gn = col0 + bn_;

    int ktiles = (Kd + BK - 1) / BK;
    int T = KT * ktiles;

    float aR[16], bR[16];
    auto loadT = [&](int t) {
        int z = t / ktiles;
        int kt = (t % ktiles) * BK;
        const float* A = d_hh[z];
        const float* sc = &d_scale[z * 512];
        const float* sh = &d_shift[z * 512];
        const float* B = Wb + (long)z * Kd * Nd;
#pragma unroll
        for (int jj = 0; jj < 16; jj++) {
            int ck = kt + akq + jj;
            float vv = 0.f;
            if (grow < M && ck < Kd)
                vv = fmaxf(fmaf(A[(long)grow * Kd + ck], sc[ck], sh[ck]), 0.f);
            aR[jj] = vv;
        }
#pragma unroll
        for (int jj = 0; jj < 16; jj++) {
            int gk = kt + bkh + jj;
            bR[jj] = (gk < Kd && gn < Nd) ? B[(long)gk * Nd + gn] : 0.f;
        }
    };

    loadT(0);
    for (int t = 0; t < T; t++) {
#pragma unroll
        for (int jj = 0; jj < 16; jj++)
            split_bf16(aR[jj], Ah[arow][akq + jj], Al[arow][akq + jj]);
#pragma unroll
        for (int jj = 0; jj < 16; jj++)
            split_bf16(bR[jj], Bh[bn_][bkh + jj], Bl[bn_][bkh + jj]);
        __syncthreads();
        if (t + 1 < T) loadT(t + 1);
        mma_slab(Ah, Al, Bh, Bl, acc, wm, wn, gid, tig);
        __syncthreads();
    }

#pragma unroll
    for (int mi = 0; mi < 4; mi++)
#pragma unroll
        for (int nj = 0; nj < 4; nj++)
#pragma unroll
            for (int r = 0; r < 4; r++) {
                int row = row0 + wm * 64 + mi * 16 + gid + ((r >> 1) << 3);
                int col = col0 + wn * 32 + nj * 8 + 2 * tig + (r & 1);
                if (row < M && col < Nd) {
                    float vv = acc[mi][nj][r] + bb[col] + bb[Nd + col] +
                               bb[2 * Nd + col];
                    if (leaky) vv = (vv > 0.f) ? vv : 0.01f * vv;
                    C[(long)row * Nd + col] = vv;
                }
            }
}

// ---------------- BN finalize ----------------
__global__ void k_bnfinal(const float* __restrict__ gB,
                          const float* __restrict__ btB, int C) {
    int k = blockIdx.x;
    int c = threadIdx.x;
    if (c >= C) return;
    float mu  = d_cs[k * 512 + c] / (float)NN;
    float var = d_css[k * 512 + c] / (float)NN - mu * mu;
    var = fmaxf(var, 0.f);
    float s = gB[k * C + c] * rsqrtf(var + BN_EPS);
    d_scale[k * 512 + c] = s;
    d_shift[k * 512 + c] = btB[k * C + c] - mu * s;
}

// ---------------- launch ----------------
extern "C" void kernel_launch(void* const* d_in, const int* in_sizes, int n_in,
                              void* d_out, int out_size) {
    // GB300 ATS pitfall: resolve REAL device addresses of __device__ symbols.
    float* p_xcur;
    cudaGetSymbolAddress((void**)&p_xcur, d_xcur);

    const float* x  = (const float*)d_in[0];
    const int*   ei = (const int*)d_in[1];
    const float* ea = (const float*)d_in[2];

    const int ciL[3] = {170, 256, 256};
    const int chL[3] = {340, 512, 512};
    const int co = 256;

    k_count<<<(KT * NE + 255) / 256, 256>>>(ei);
    k_scan<<<KT, 1024>>>();
    k_fill<<<(KT * NE + 255) / 256, 256>>>(ei);

    const float* xin = x;
    for (int l = 0; l < 3; l++) {
        int ci = ciL[l], ch = chL[l];
        const float* We = (const float*)d_in[3 + l * 8 + 0];
        const float* be = (const float*)d_in[3 + l * 8 + 1];
        const float* Wa = (const float*)d_in[3 + l * 8 + 2];
        const float* ba = (const float*)d_in[3 + l * 8 + 3];
        const float* g  = (const float*)d_in[3 + l * 8 + 4];
        const float* bt = (const float*)d_in[3 + l * 8 + 5];
        const float* Wb = (const float*)d_in[3 + l * 8 + 6];
        const float* bb = (const float*)d_in[3 + l * 8 + 7];
        float* dest = (l == 2) ? (float*)d_out : p_xcur;

        dim3 ga(NN, KT);
        k_aggr<<<ga, 256>>>(xin, ei, ea, We, be, ci);

        dim3 g1((ch + BN - 1) / BN, (NN + BM - 1) / BM, KT);
        k_gemm1<<<g1, 256>>>(Wa, ba, NN, ci, ch);

        k_bnfinal<<<KT, 512>>>(g, bt, ch);

        dim3 g2((co + BN - 1) / BN, (NN + BM - 1) / BM);
        k_gemm2<<<g2, 256>>>(Wb, bb, dest, NN, ch, co, (l < 2) ? 1 : 0);

        if (l < 2) xin = p_xcur;
    }
}